// round 17
// baseline (speedup 1.0000x reference)
#include <cuda_runtime.h>
#include <cuda_bf16.h>
#include <cstdint>
#include <math.h>

#define B_    2
#define T_    2048
#define TREF_ 512
#define C_    768
#define H_    12
#define D_    64
#define SK_   (T_ + TREF_)
#define L2E   1.4426950408889634f
#define QSC   (0.125f * L2E)

__device__ __nv_bfloat16 g_xh[(size_t)B_ * T_ * C_],    g_xl[(size_t)B_ * T_ * C_];
__device__ __nv_bfloat16 g_rh[(size_t)B_ * TREF_ * C_], g_rl[(size_t)B_ * TREF_ * C_];
__device__ __nv_bfloat16 g_wh[6 * C_ * C_],             g_wl[6 * C_ * C_];
__device__ __nv_bfloat16 g_yh[(size_t)B_ * T_ * C_],    g_yl[(size_t)B_ * T_ * C_];
__device__ __nv_bfloat16 g_qh[(size_t)B_ * H_ * T_  * D_], g_ql[(size_t)B_ * H_ * T_ * D_];
__device__ __nv_bfloat16 g_kh[(size_t)B_ * H_ * SK_ * D_], g_kl[(size_t)B_ * H_ * SK_ * D_];
__device__ __nv_bfloat16 g_vth[(size_t)B_ * H_ * D_ * SK_], g_vtl[(size_t)B_ * H_ * D_ * SK_];

// ---------------- helpers ----------------
__device__ __forceinline__ uint32_t smem_u32(const void* p) {
    uint32_t a;
    asm("{ .reg .u64 t; cvta.to.shared.u64 t, %1; cvt.u32.u64 %0, t; }" : "=r"(a) : "l"(p));
    return a;
}
#define SW128(o) ((o) ^ (((o) >> 3) & 0x70))

__device__ __forceinline__ void ldmx4(uint32_t* r, uint32_t addr) {
    asm volatile("ldmatrix.sync.aligned.m8n8.x4.shared.b16 {%0,%1,%2,%3}, [%4];"
                 : "=r"(r[0]), "=r"(r[1]), "=r"(r[2]), "=r"(r[3]) : "r"(addr));
}
__device__ __forceinline__ void mma_bf16(float* d, const uint32_t* a, const uint32_t* b) {
    asm volatile("mma.sync.aligned.m16n8k16.row.col.f32.bf16.bf16.f32 "
                 "{%0,%1,%2,%3}, {%4,%5,%6,%7}, {%8,%9}, {%0,%1,%2,%3};"
                 : "+f"(d[0]), "+f"(d[1]), "+f"(d[2]), "+f"(d[3])
                 : "r"(a[0]), "r"(a[1]), "r"(a[2]), "r"(a[3]), "r"(b[0]), "r"(b[1]));
}
__device__ __forceinline__ void cp16(uint32_t saddr, const void* g) {
    asm volatile("cp.async.cg.shared.global [%0], [%1], 16;" :: "r"(saddr), "l"(g));
}
#define CP_COMMIT() asm volatile("cp.async.commit_group;" ::: "memory")
#define CP_WAIT(n)  asm volatile("cp.async.wait_group %0;" :: "n"(n) : "memory")

__device__ __forceinline__ float ex2(float x) {
    float r;
    asm("ex2.approx.f32 %0, %1;" : "=f"(r) : "f"(x));
    return r;
}
__device__ __forceinline__ void bf16split2(float f0, float f1, uint32_t& hw, uint32_t& lw) {
    __nv_bfloat16 h0 = __float2bfloat16(f0), h1 = __float2bfloat16(f1);
    __nv_bfloat162 hp(h0, h1);
    __nv_bfloat162 lp(__float2bfloat16(f0 - __bfloat162float(h0)),
                      __float2bfloat16(f1 - __bfloat162float(h1)));
    hw = *(uint32_t*)&hp; lw = *(uint32_t*)&lp;
}

// ---------------- splits ----------------
#define NX4 (B_ * T_ * C_ / 4)
#define NR4 (B_ * TREF_ * C_ / 4)
__global__ __launch_bounds__(256)
void splitXR(const float* __restrict__ x, const float* __restrict__ ref,
             __nv_bfloat16* __restrict__ xh, __nv_bfloat16* __restrict__ xl,
             __nv_bfloat16* __restrict__ rh, __nv_bfloat16* __restrict__ rl)
{
    const int bx = blockIdx.x;
    const float* src; __nv_bfloat16 *hi, *lo; int i;
    if (bx < NX4 / 256) { src = x;   hi = xh; lo = xl; i = bx * 256 + threadIdx.x; }
    else                { src = ref; hi = rh; lo = rl; i = (bx - NX4 / 256) * 256 + threadIdx.x; }
    const float4 a = ((const float4*)src)[i];
    uint32_t h0, l0, h1, l1;
    bf16split2(a.x, a.y, h0, l0);
    bf16split2(a.z, a.w, h1, l1);
    ((uint32_t*)hi)[2*i+0] = h0; ((uint32_t*)hi)[2*i+1] = h1;
    ((uint32_t*)lo)[2*i+0] = l0; ((uint32_t*)lo)[2*i+1] = l1;
}

__global__ __launch_bounds__(256)
void split6_kernel(const float* w0, const float* w1, const float* w2,
                   const float* w3, const float* w4, const float* w5,
                   __nv_bfloat16* __restrict__ hi, __nv_bfloat16* __restrict__ lo)
{
    const float* ws[6] = {w0, w1, w2, w3, w4, w5};
    const int wi = blockIdx.y;
    const int i = blockIdx.x * 256 + threadIdx.x;
    const float4 a = ((const float4*)ws[wi])[i];
    const size_t o = (size_t)wi * (C_ * C_ / 2) + i * 2;
    uint32_t h0, l0, h1, l1;
    bf16split2(a.x, a.y, h0, l0);
    bf16split2(a.z, a.w, h1, l1);
    ((uint32_t*)hi)[o + 0] = h0; ((uint32_t*)hi)[o + 1] = h1;
    ((uint32_t*)lo)[o + 0] = l0; ((uint32_t*)lo)[o + 1] = l1;
}

// ---------------- shared GEMM machinery ----------------
#define STSZ  49152
#define GSMEM (2 * STSZ)

__device__ __forceinline__ void cp_stage(uint32_t sbase,
    const __nv_bfloat16* __restrict__ Ah, const __nv_bfloat16* __restrict__ Al,
    const __nv_bfloat16* __restrict__ Bh, const __nv_bfloat16* __restrict__ Bl,
    int m0, int n0, int k0, int tid)
{
    #pragma unroll
    for (int i = 0; i < 4; i++) {
        const int u = tid + 256 * i, r = u >> 3, g = u & 7;
        const size_t go = (size_t)(m0 + r) * C_ + k0 + g * 8;
        const uint32_t so = SW128((uint32_t)(r * 128 + g * 16));
        cp16(sbase + so,         Ah + go);
        cp16(sbase + 16384 + so, Al + go);
    }
    #pragma unroll
    for (int i = 0; i < 2; i++) {
        const int u = tid + 256 * i, r = u >> 3, g = u & 7;
        const size_t go = (size_t)(n0 + r) * C_ + k0 + g * 8;
        const uint32_t so = SW128((uint32_t)(r * 128 + g * 16));
        cp16(sbase + 32768 + so, Bh + go);
        cp16(sbase + 40960 + so, Bl + go);
    }
}

__device__ __forceinline__ void mma_block3(float Dv[2][4][4],
    uint32_t baseAh, uint32_t baseAl, uint32_t baseBh, uint32_t baseBl,
    int arow0, uint32_t akb, int brow0, uint32_t bkb)
{
    #pragma unroll
    for (int ks = 0; ks < 4; ks++) {
        uint32_t ah[2][4], al[2][4], bh[2][4], bl[2][4];
        #pragma unroll
        for (int ms = 0; ms < 2; ms++) {
            const uint32_t off = SW128((uint32_t)((arow0 + ms * 16) * 128) + ks * 32 + akb);
            ldmx4(ah[ms], baseAh + off);
            ldmx4(al[ms], baseAl + off);
        }
        #pragma unroll
        for (int nj = 0; nj < 2; nj++) {
            const uint32_t off = SW128((uint32_t)((brow0 + nj * 16) * 128) + ks * 32 + bkb);
            ldmx4(bh[nj], baseBh + off);
            ldmx4(bl[nj], baseBl + off);
        }
        #pragma unroll
        for (int ms = 0; ms < 2; ms++)
            #pragma unroll
            for (int ns = 0; ns < 4; ns++) {
                const uint32_t* fh = &bh[ns >> 1][(ns & 1) * 2];
                const uint32_t* fl = &bl[ns >> 1][(ns & 1) * 2];
                mma_bf16(Dv[ms][ns], ah[ms], fh);
                mma_bf16(Dv[ms][ns], ah[ms], fl);
                mma_bf16(Dv[ms][ns], al[ms], fh);
            }
    }
}

// ---------------- fused QKV/RK/RV projection GEMM (5 segments) -------------
// grid.y layout: Q[0,32) K[32,64) RK[64,72) V[72,104) RV[104,112)
__global__ __launch_bounds__(256)
void qkv_gemm(const float* __restrict__ bq, const float* __restrict__ bk,
              const float* __restrict__ brk, const float* __restrict__ bv,
              const float* __restrict__ brv)
{
    extern __shared__ char smem[];
    const uint32_t sb = smem_u32(smem);
    const int tid = threadIdx.x, lane = tid & 31, wid = tid >> 5;
    const int wm = wid & 3, wn = wid >> 2;
    const int by = blockIdx.y;

    int seg, mt;
    if      (by < 32)  { seg = 0; mt = by; }
    else if (by < 64)  { seg = 1; mt = by - 32; }
    else if (by < 72)  { seg = 2; mt = by - 64; }
    else if (by < 104) { seg = 3; mt = by - 72; }
    else               { seg = 4; mt = by - 104; }
    const bool isRef = (seg == 2 || seg == 4);
    const __nv_bfloat16* Ah = isRef ? g_rh : g_xh;
    const __nv_bfloat16* Al = isRef ? g_rl : g_xl;
    const int widx = (seg == 0) ? 0 : (seg == 1) ? 1 : (seg == 2) ? 3 : (seg == 3) ? 2 : 4;
    const __nv_bfloat16* Wh = g_wh + (size_t)widx * C_ * C_;
    const __nv_bfloat16* Wl = g_wl + (size_t)widx * C_ * C_;
    const float* bias = (seg == 0) ? bq : (seg == 1) ? bk : (seg == 2) ? brk
                       : (seg == 3) ? bv : brv;
    const int Trows = isRef ? TREF_ : T_;
    const int toff  = isRef ? T_ : 0;
    const int SKo   = (seg == 0) ? T_ : SK_;
    const float oscale = (seg == 0) ? QSC : 1.f;
    const int mode = (seg >= 3) ? 3 : 2;
    const int n0 = blockIdx.x * 64;
    const int m0 = mt * 128;

    float D[2][4][4] = {};
    cp_stage(sb, Ah, Al, Wh, Wl, m0, n0, 0, tid);
    CP_COMMIT();

    const int arow0 = wm * 32 + (lane & 15);
    const uint32_t akb = ((uint32_t)(lane >> 4)) << 4;
    const int brow0 = wn * 32 + ((lane >> 4) << 3) + (lane & 7);
    const uint32_t bkb = ((uint32_t)((lane >> 3) & 1)) << 4;

    #pragma unroll 1
    for (int c = 0; c < 12; c++) {
        if (c + 1 < 12) {
            cp_stage(sb + ((c + 1) & 1) * STSZ, Ah, Al, Wh, Wl, m0, n0, (c + 1) * 64, tid);
            CP_COMMIT();
            CP_WAIT(1);
        } else CP_WAIT(0);
        __syncthreads();
        const uint32_t bA = sb + (c & 1) * STSZ;
        mma_block3(D, bA, bA + 16384, bA + 32768, bA + 40960, arow0, akb, brow0, bkb);
        __syncthreads();
    }

    const int h = n0 >> 6;
    if (mode == 3) {
        float* S = (float*)smem;                       // 128 x 68 fp32
        #pragma unroll
        for (int ns = 0; ns < 4; ns++) {
            const int col = wn * 32 + ns * 8 + (lane & 3) * 2;
            const float b0 = bias[n0 + col], b1 = bias[n0 + col + 1];
            #pragma unroll
            for (int ms = 0; ms < 2; ms++)
                #pragma unroll
                for (int half = 0; half < 2; half++) {
                    const int r = wm * 32 + ms * 16 + (lane >> 2) + half * 8;
                    *(float2*)&S[r * 68 + col] =
                        make_float2(D[ms][ns][half*2] + b0, D[ms][ns][half*2+1] + b1);
                }
        }
        __syncthreads();
        const int bi = m0 / Trows, t0 = m0 % Trows;
        const int bh = bi * H_ + h;
        #pragma unroll
        for (int it = 0; it < 4; it++) {
            const int u = tid + 256 * it, d = u >> 4, ch = u & 15;
            float f[8];
            #pragma unroll
            for (int p = 0; p < 8; p++) f[p] = S[(ch * 8 + p) * 68 + d];
            uint32_t hw[4], lw[4];
            #pragma unroll
            for (int p = 0; p < 4; p++) bf16split2(f[2*p], f[2*p+1], hw[p], lw[p]);
            const size_t o = ((size_t)bh * D_ + d) * SK_ + toff + t0 + ch * 8;
            *(uint4*)(g_vth + o) = make_uint4(hw[0], hw[1], hw[2], hw[3]);
            *(uint4*)(g_vtl + o) = make_uint4(lw[0], lw[1], lw[2], lw[3]);
        }
    } else {
        __nv_bfloat16* oh = (seg == 0) ? g_qh : g_kh;
        __nv_bfloat16* ol = (seg == 0) ? g_ql : g_kl;
        #pragma unroll
        for (int ns = 0; ns < 4; ns++) {
            const int col = n0 + wn * 32 + ns * 8 + (lane & 3) * 2;
            const float b0 = bias[col], b1 = bias[col + 1];
            #pragma unroll
            for (int ms = 0; ms < 2; ms++) {
                const int r0 = m0 + wm * 32 + ms * 16 + (lane >> 2);
                #pragma unroll
                for (int half = 0; half < 2; half++) {
                    const int m = r0 + half * 8;
                    const int bi = m / Trows, t = m % Trows, d = col - n0;
                    const size_t idx = ((size_t)(bi * H_ + h) * SKo + t + toff) * D_ + d;
                    uint32_t hw, lw;
                    bf16split2((D[ms][ns][half*2+0] + b0) * oscale,
                               (D[ms][ns][half*2+1] + b1) * oscale, hw, lw);
                    *(uint32_t*)(oh + idx) = hw;
                    *(uint32_t*)(ol + idx) = lw;
                }
            }
        }
    }
}

// ---------------- output projection GEMM (fp32 out) ----------------
__global__ __launch_bounds__(256)
void out_gemm(const float* __restrict__ bias, float* __restrict__ out)
{
    extern __shared__ char smem[];
    const uint32_t sb = smem_u32(smem);
    const int tid = threadIdx.x, lane = tid & 31, wid = tid >> 5;
    const int wm = wid & 3, wn = wid >> 2;
    const int n0 = blockIdx.x * 64, m0 = blockIdx.y * 128;
    const __nv_bfloat16* Wh = g_wh + (size_t)5 * C_ * C_;
    const __nv_bfloat16* Wl = g_wl + (size_t)5 * C_ * C_;

    float D[2][4][4] = {};
    cp_stage(sb, g_yh, g_yl, Wh, Wl, m0, n0, 0, tid);
    CP_COMMIT();

    const int arow0 = wm * 32 + (lane & 15);
    const uint32_t akb = ((uint32_t)(lane >> 4)) << 4;
    const int brow0 = wn * 32 + ((lane >> 4) << 3) + (lane & 7);
    const uint32_t bkb = ((uint32_t)((lane >> 3) & 1)) << 4;

    #pragma unroll 1
    for (int c = 0; c < 12; c++) {
        if (c + 1 < 12) {
            cp_stage(sb + ((c + 1) & 1) * STSZ, g_yh, g_yl, Wh, Wl, m0, n0, (c + 1) * 64, tid);
            CP_COMMIT();
            CP_WAIT(1);
        } else CP_WAIT(0);
        __syncthreads();
        const uint32_t bA = sb + (c & 1) * STSZ;
        mma_block3(D, bA, bA + 16384, bA + 32768, bA + 40960, arow0, akb, brow0, bkb);
        __syncthreads();
    }

    #pragma unroll
    for (int ns = 0; ns < 4; ns++) {
        const int col = n0 + wn * 32 + ns * 8 + (lane & 3) * 2;
        const float b0 = bias[col], b1 = bias[col + 1];
        #pragma unroll
        for (int ms = 0; ms < 2; ms++) {
            const int r0 = m0 + wm * 32 + ms * 16 + (lane >> 2);
            #pragma unroll
            for (int half = 0; half < 2; half++) {
                const int m = r0 + half * 8;
                *(float2*)(out + (size_t)m * C_ + col) =
                    make_float2(D[ms][ns][half*2+0] + b0, D[ms][ns][half*2+1] + b1);
            }
        }
    }
}

// ---------------- flash attention: 64-row blocks, 3-stage pipeline ---------
#define AS_QH  0
#define AS_QL  8192
#define AS_STG 16384           /* +s*32768, s in {0,1,2}: KH | KL | VTH | VTL */
#define ASMEM  (16384 + 3 * 32768)
#define NKB    (SK_ / 64)

__device__ __forceinline__ void attn_prefetch(uint32_t st, int bh, int kb,
    const __nv_bfloat16* __restrict__ kh, const __nv_bfloat16* __restrict__ kl,
    const __nv_bfloat16* __restrict__ vth, const __nv_bfloat16* __restrict__ vtl,
    int tid)
{
    const size_t kbase = ((size_t)bh * SK_ + kb * 64) * D_;
    const size_t vbase = (size_t)bh * D_ * SK_ + kb * 64;
    #pragma unroll
    for (int it = 0; it < 2; it++) {
        const int u = tid + 256 * it, r = u >> 3, g = u & 7;
        const uint32_t so = SW128((uint32_t)(r * 128 + g * 16));
        cp16(st + so,         kh + kbase + (size_t)r * D_ + g * 8);
        cp16(st + 8192 + so,  kl + kbase + (size_t)r * D_ + g * 8);
        cp16(st + 16384 + so, vth + vbase + (size_t)r * SK_ + g * 8);
        cp16(st + 24576 + so, vtl + vbase + (size_t)r * SK_ + g * 8);
    }
}

__global__ __launch_bounds__(256)
void attn_mma(const int* __restrict__ mask, const float* __restrict__ rel,
              const __nv_bfloat16* __restrict__ qh, const __nv_bfloat16* __restrict__ ql,
              const __nv_bfloat16* __restrict__ kh, const __nv_bfloat16* __restrict__ kl,
              const __nv_bfloat16* __restrict__ vth, const __nv_bfloat16* __restrict__ vtl,
              __nv_bfloat16* __restrict__ yh, __nv_bfloat16* __restrict__ yl)
{
    extern __shared__ char smem[];
    const uint32_t sb = smem_u32(smem);
    const float NI = __int_as_float(0xff800000);

    const int tid = threadIdx.x, lane = tid & 31, wid = tid >> 5;
    const int wr = wid & 3, wk = wid >> 2;
    const int qb = blockIdx.x, hh = blockIdx.y, bb = blockIdx.z;
    const int tq0 = qb * 64, bh = bb * H_ + hh;
    const int rl0 = wr * 16 + (lane >> 2);
    const int r0g = tq0 + rl0;

    // group 0: Q + stage 0 ; group 1: stage 1
    {
        const size_t qbase = ((size_t)bh * T_ + tq0) * D_;
        #pragma unroll
        for (int it = 0; it < 2; it++) {
            const int u = tid + 256 * it, r = u >> 3, g = u & 7;
            const uint32_t so = SW128((uint32_t)(r * 128 + g * 16));
            cp16(sb + AS_QH + so, qh + qbase + (size_t)r * D_ + g * 8);
            cp16(sb + AS_QL + so, ql + qbase + (size_t)r * D_ + g * 8);
        }
        attn_prefetch(sb + AS_STG, bh, 0, kh, kl, vth, vtl, tid);
        CP_COMMIT();
        attn_prefetch(sb + AS_STG + 32768, bh, 1, kh, kl, vth, vtl, tid);
        CP_COMMIT();
    }

    float O[8][4] = {};
    float mp0 = NI, mp1 = NI, l0 = 0.f, l1 = 0.f;

    #pragma unroll 1
    for (int kb = 0; kb < NKB; kb++) {
        if (kb + 2 < NKB) {
            attn_prefetch(sb + AS_STG + ((kb + 2) % 3) * 32768, bh, kb + 2,
                          kh, kl, vth, vtl, tid);
            CP_COMMIT();
            CP_WAIT(2);
        } else if (kb + 1 < NKB) CP_WAIT(1);
        else CP_WAIT(0);
        __syncthreads();

        const uint32_t stg = sb + AS_STG + (kb % 3) * 32768;

        // ---- QK over this warp's 32 keys ----
        float Dq[4][4] = {};
        #pragma unroll
        for (int ks = 0; ks < 4; ks++) {
            uint32_t qfh[4], qfl[4];
            const uint32_t qoff =
                SW128((uint32_t)((wr * 16 + (lane & 15)) * 128) + ks * 32 + (((uint32_t)(lane >> 4)) << 4));
            ldmx4(qfh, sb + AS_QH + qoff);
            ldmx4(qfl, sb + AS_QL + qoff);
            uint32_t kfh[2][4], kfl[2][4];
            #pragma unroll
            for (int nj = 0; nj < 2; nj++) {
                const uint32_t off =
                    SW128((uint32_t)((wk * 32 + nj * 16 + ((lane >> 4) << 3) + (lane & 7)) * 128) +
                          ks * 32 + (((uint32_t)((lane >> 3) & 1)) << 4));
                ldmx4(kfh[nj], stg + off);
                ldmx4(kfl[nj], stg + 8192 + off);
            }
            #pragma unroll
            for (int ns = 0; ns < 4; ns++) {
                const uint32_t* fh = &kfh[ns >> 1][(ns & 1) * 2];
                const uint32_t* fl = &kfl[ns >> 1][(ns & 1) * 2];
                mma_bf16(Dq[ns], qfh, fh);
                mma_bf16(Dq[ns], qfh, fl);
                mma_bf16(Dq[ns], qfl, fh);
            }
        }

        // ---- bias (mask/rel) ----
        if (kb < T_ / 64) {
            const int colb = kb * 64 + wk * 32 + (lane & 3) * 2;
            const size_t mrow0 = ((size_t)bb * T_ + r0g) * T_ + colb;
            const size_t rrow0 = ((size_t)hh * T_ + r0g) * T_ + colb;
            #pragma unroll
            for (int ns = 0; ns < 4; ns++) {
                const int o = ns * 8;
                const int2   mv0 = *(const int2*)  (mask + mrow0 + o);
                const float2 rv0 = *(const float2*)(rel  + rrow0 + o);
                Dq[ns][0] = mv0.x ? NI : fmaf(rv0.x, L2E, Dq[ns][0]);
                Dq[ns][1] = mv0.y ? NI : fmaf(rv0.y, L2E, Dq[ns][1]);
                const int2   mv1 = *(const int2*)  (mask + mrow0 + (size_t)8 * T_ + o);
                const float2 rv1 = *(const float2*)(rel  + rrow0 + (size_t)8 * T_ + o);
                Dq[ns][2] = mv1.x ? NI : fmaf(rv1.x, L2E, Dq[ns][2]);
                Dq[ns][3] = mv1.y ? NI : fmaf(rv1.y, L2E, Dq[ns][3]);
            }
        }

        // ---- per-warp online softmax ----
        float m0l = NI, m1l = NI;
        #pragma unroll
        for (int ns = 0; ns < 4; ns++) {
            m0l = fmaxf(m0l, fmaxf(Dq[ns][0], Dq[ns][1]));
            m1l = fmaxf(m1l, fmaxf(Dq[ns][2], Dq[ns][3]));
        }
        m0l = fmaxf(m0l, __shfl_xor_sync(0xffffffffu, m0l, 1));
        m0l = fmaxf(m0l, __shfl_xor_sync(0xffffffffu, m0l, 2));
        m1l = fmaxf(m1l, __shfl_xor_sync(0xffffffffu, m1l, 1));
        m1l = fmaxf(m1l, __shfl_xor_sync(0xffffffffu, m1l, 2));
        const float mn0 = fmaxf(mp0, m0l), mn1 = fmaxf(mp1, m1l);
        const float c0 = (mp0 == NI) ? 0.f : ex2(mp0 - mn0);
        const float c1 = (mp1 == NI) ? 0.f : ex2(mp1 - mn1);
        float s0 = 0.f, s1 = 0.f;
        #pragma unroll
        for (int ns = 0; ns < 4; ns++) {
            float p;
            p = (Dq[ns][0] == NI || mn0 == NI) ? 0.f : ex2(Dq[ns][0] - mn0); Dq[ns][0] = p; s0 += p;
            p = (Dq[ns][1] == NI || mn0 == NI) ? 0.f : ex2(Dq[ns][1] - mn0); Dq[ns][1] = p; s0 += p;
            p = (Dq[ns][2] == NI || mn1 == NI) ? 0.f : ex2(Dq[ns][2] - mn1); Dq[ns][2] = p; s1 += p;
            p = (Dq[ns][3] == NI || mn1 == NI) ? 0.f : ex2(Dq[ns][3] - mn1); Dq[ns][3] = p; s1 += p;
        }
        s0 += __shfl_xor_sync(0xffffffffu, s0, 1);
        s0 += __shfl_xor_sync(0xffffffffu, s0, 2);
        s1 += __shfl_xor_sync(0xffffffffu, s1, 1);
        s1 += __shfl_xor_sync(0xffffffffu, s1, 2);
        l0 = l0 * c0 + s0;  l1 = l1 * c1 + s1;
        mp0 = mn0;          mp1 = mn1;

        // ---- P fragments (C->A identity) ----
        uint32_t ph_[2][4], pl_[2][4];
        #pragma unroll
        for (int j = 0; j < 2; j++) {
            bf16split2(Dq[2*j  ][0], Dq[2*j  ][1], ph_[j][0], pl_[j][0]);
            bf16split2(Dq[2*j  ][2], Dq[2*j  ][3], ph_[j][1], pl_[j][1]);
            bf16split2(Dq[2*j+1][0], Dq[2*j+1][1], ph_[j][2], pl_[j][2]);
            bf16split2(Dq[2*j+1][2], Dq[2*j+1][3], ph_[j][3], pl_[j][3]);
        }

        // ---- O rescale + PV ----
        #pragma unroll
        for (int ns = 0; ns < 8; ns++) {
            O[ns][0] *= c0; O[ns][1] *= c0; O[ns][2] *= c1; O[ns][3] *= c1;
        }
        #pragma unroll
        for (int j = 0; j < 2; j++) {
            uint32_t vfh[4][4], vfl[4][4];
            #pragma unroll
            for (int nj = 0; nj < 4; nj++) {
                const uint32_t off =
                    SW128((uint32_t)((nj * 16 + ((lane >> 4) << 3) + (lane & 7)) * 128) +
                          (wk * 2 + j) * 32 + (((uint32_t)((lane >> 3) & 1)) << 4));
                ldmx4(vfh[nj], stg + 16384 + off);
                ldmx4(vfl[nj], stg + 24576 + off);
            }
            #pragma unroll
            for (int ns = 0; ns < 8; ns++) {
                const uint32_t* fh = &vfh[ns >> 1][(ns & 1) * 2];
                const uint32_t* fl = &vfl[ns >> 1][(ns & 1) * 2];
                mma_bf16(O[ns], ph_[j], fh);
                mma_bf16(O[ns], ph_[j], fl);
                mma_bf16(O[ns], pl_[j], fh);
            }
        }
        __syncthreads();     // protect stage reuse (distance-2 prefetch)
    }

    // ---- split-KV merge across wk halves ----
    float* Osh = (float*)(smem + AS_STG);
    float* msh = (float*)(smem + AS_STG + 64 * 68 * 4);
    float* lsh = msh + 64;
    __syncthreads();
    if (wk == 1) {
        #pragma unroll
        for (int ns = 0; ns < 8; ns++) {
            const int d = ns * 8 + (lane & 3) * 2;
            *(float2*)&Osh[rl0 * 68 + d]       = make_float2(O[ns][0], O[ns][1]);
            *(float2*)&Osh[(rl0 + 8) * 68 + d] = make_float2(O[ns][2], O[ns][3]);
        }
        if ((lane & 3) == 0) {
            msh[rl0] = mp0; lsh[rl0] = l0;
            msh[rl0 + 8] = mp1; lsh[rl0 + 8] = l1;
        }
    }
    __syncthreads();
    if (wk == 0) {
        const float mB0 = msh[rl0],     lB0 = lsh[rl0];
        const float mB1 = msh[rl0 + 8], lB1 = lsh[rl0 + 8];
        const float mm0 = fmaxf(mp0, mB0), mm1 = fmaxf(mp1, mB1);
        const float cA0 = ex2(mp0 - mm0), cB0 = ex2(mB0 - mm0);
        const float cA1 = ex2(mp1 - mm1), cB1 = ex2(mB1 - mm1);
        const float inv0 = 1.0f / (l0 * cA0 + lB0 * cB0);
        const float inv1 = 1.0f / (l1 * cA1 + lB1 * cB1);
        #pragma unroll
        for (int ns = 0; ns < 8; ns++) {
            const int d = ns * 8 + (lane & 3) * 2;
            const float2 b0 = *(const float2*)&Osh[rl0 * 68 + d];
            const float2 b1 = *(const float2*)&Osh[(rl0 + 8) * 68 + d];
            const size_t idx0 = ((size_t)bb * T_ + r0g) * C_ + hh * D_ + d;
            uint32_t hw, lw;
            bf16split2((O[ns][0] * cA0 + b0.x * cB0) * inv0,
                       (O[ns][1] * cA0 + b0.y * cB0) * inv0, hw, lw);
            *(uint32_t*)(yh + idx0) = hw;
            *(uint32_t*)(yl + idx0) = lw;
            bf16split2((O[ns][2] * cA1 + b1.x * cB1) * inv1,
                       (O[ns][3] * cA1 + b1.y * cB1) * inv1, hw, lw);
            *(uint32_t*)(yh + idx0 + (size_t)8 * C_) = hw;
            *(uint32_t*)(yl + idx0 + (size_t)8 * C_) = lw;
        }
    }
}

// ---------------------------------------------------------------------------
extern "C" void kernel_launch(void* const* d_in, const int* in_sizes, int n_in,
                              void* d_out, int out_size)
{
    const float* x    = (const float*)d_in[0];
    const int*   mask = (const int*)  d_in[1];
    const float* rel  = (const float*)d_in[2];
    const float* ref  = (const float*)d_in[3];
    const float* W[6] = {(const float*)d_in[4], (const float*)d_in[6], (const float*)d_in[8],
                         (const float*)d_in[10], (const float*)d_in[12], (const float*)d_in[14]};
    const float* bias[6] = {(const float*)d_in[5], (const float*)d_in[7], (const float*)d_in[9],
                            (const float*)d_in[11], (const float*)d_in[13], (const float*)d_in[15]};
    float* out = (float*)d_out;

    __nv_bfloat16 *xh, *xl, *rh, *rl, *wh, *wl, *yh, *yl, *qh, *ql, *kh, *kl, *vth, *vtl;
    cudaGetSymbolAddress((void**)&xh, g_xh);  cudaGetSymbolAddress((void**)&xl, g_xl);
    cudaGetSymbolAddress((void**)&rh, g_rh);  cudaGetSymbolAddress((void**)&rl, g_rl);
    cudaGetSymbolAddress((void**)&wh, g_wh);  cudaGetSymbolAddress((void**)&wl, g_wl);
    cudaGetSymbolAddress((void**)&yh, g_yh);  cudaGetSymbolAddress((void**)&yl, g_yl);
    cudaGetSymbolAddress((void**)&qh, g_qh);  cudaGetSymbolAddress((void**)&ql, g_ql);
    cudaGetSymbolAddress((void**)&kh, g_kh);  cudaGetSymbolAddress((void**)&kl, g_kl);
    cudaGetSymbolAddress((void**)&vth, g_vth); cudaGetSymbolAddress((void**)&vtl, g_vtl);

    cudaFuncSetAttribute(qkv_gemm, cudaFuncAttributeMaxDynamicSharedMemorySize, GSMEM);
    cudaFuncSetAttribute(out_gemm, cudaFuncAttributeMaxDynamicSharedMemorySize, GSMEM);
    cudaFuncSetAttribute(attn_mma, cudaFuncAttributeMaxDynamicSharedMemorySize, ASMEM);

    const dim3 blk(256);

    // 1: x + ref splits
    splitXR<<<NX4 / 256 + NR4 / 256, blk>>>(x, ref, xh, xl, rh, rl);
    // 2: all 6 weight splits
    split6_kernel<<<dim3(C_ * C_ / 4 / 256, 6), blk>>>(W[0], W[1], W[2], W[3], W[4], W[5], wh, wl);
    // 3: ALL projections (Q/K/RK/V/RV) in one segmented launch (12 x 112)
    qkv_gemm<<<dim3(C_ / 64, 112), blk, GSMEM>>>(bias[0], bias[1], bias[3], bias[2], bias[4]);
    // 4: attention (PROFILED SLOT)
    attn_mma<<<dim3(T_ / 64, H_, B_), blk, ASMEM>>>(mask, rel, qh, ql, kh, kl, vth, vtl, yh, yl);
    // 5: output projection
    out_gemm<<<dim3(C_ / 64, (B_ * T_) / 128), blk, GSMEM>>>(bias[5], out);
}